// round 8
// baseline (speedup 1.0000x reference)
#include <cuda_runtime.h>
#include <cuda_bf16.h>
#include <math.h>

// Problem constants
#define NROW 384          // N = 2*bs
#define BSZ  192
#define DIM  1024
#define NM1  383          // N-1
#define MDEN 56328576.0   // N*(N-1)^2
#define TK   48           // gram tile
#define NT   8            // tiles per side (384/48)

// Scratch (device globals; no allocation allowed)
__device__ float g_d[4][NROW * NROW];   // k-split partial dot products
__device__ float g_sqp[4 * NROW];       // k-split partial squared norms
__device__ float g_row[2 * NROW];       // per (row, half) partials
__device__ int   g_cnt;                 // zero-init; last block resets -> replay-safe

__device__ __forceinline__ const float* frow(const float* f, int r) {
    return f + (r < BSZ ? r * (2 * DIM) : (r - BSZ) * (2 * DIM) + DIM);
}

// ---- packed f32x2 helpers ----
__device__ __forceinline__ unsigned long long pk2(float lo, float hi) {
    unsigned long long r;
    asm("mov.b64 %0, {%1, %2};" : "=l"(r) : "f"(lo), "f"(hi));
    return r;
}
__device__ __forceinline__ unsigned long long add2(unsigned long long a, unsigned long long b) {
    unsigned long long r;
    asm("add.rn.f32x2 %0, %1, %2;" : "=l"(r) : "l"(a), "l"(b));
    return r;
}
__device__ __forceinline__ float mulhl(unsigned long long a) {
    float lo, hi;
    asm("mov.b64 {%0, %1}, %2;" : "=f"(lo), "=f"(hi) : "l"(a));
    return lo * hi;
}

// ---------------------------------------------------------------------------
// Kernel 1: symmetric tiled Gram partials with k-split (unchanged).
// ---------------------------------------------------------------------------
#define FMAK(cmp) \
    acc00 = fmaf(a0.cmp, b0v.cmp, acc00); acc01 = fmaf(a0.cmp, b1v.cmp, acc01); acc02 = fmaf(a0.cmp, b2v.cmp, acc02); \
    acc10 = fmaf(a1.cmp, b0v.cmp, acc10); acc11 = fmaf(a1.cmp, b1v.cmp, acc11); acc12 = fmaf(a1.cmp, b2v.cmp, acc12); \
    acc20 = fmaf(a2.cmp, b0v.cmp, acc20); acc21 = fmaf(a2.cmp, b1v.cmp, acc21); acc22 = fmaf(a2.cmp, b2v.cmp, acc22);

__global__ __launch_bounds__(256) void gram_kernel(const float* __restrict__ feats) {
    __shared__ float As[TK][68];
    __shared__ float BsT[64][49];

    int bid = blockIdx.x;
    int p = bid >> 2, kz = bid & 3;
    int a = 0, rem = p;
    while (rem >= NT - a) { rem -= NT - a; a++; }
    int b = a + rem;

    int tid = threadIdx.x;
    int ty = tid >> 4, tx = tid & 15;
    int r0 = a * TK, c0 = b * TK;
    int kbase = kz * 256;

    float acc00 = 0.f, acc01 = 0.f, acc02 = 0.f;
    float acc10 = 0.f, acc11 = 0.f, acc12 = 0.f;
    float acc20 = 0.f, acc21 = 0.f, acc22 = 0.f;

    for (int ch = 0; ch < 4; ch++) {
        int kc = kbase + ch * 64;
        #pragma unroll
        for (int it = 0; it < 3; it++) {
            int q = tid + it * 256;
            int r = q >> 4, kq = (q & 15) << 2;
            float4 av = *(const float4*)(frow(feats, r0 + r) + kc + kq);
            float4 bv = *(const float4*)(frow(feats, c0 + r) + kc + kq);
            *(float4*)&As[r][kq] = av;
            BsT[kq + 0][r] = bv.x; BsT[kq + 1][r] = bv.y;
            BsT[kq + 2][r] = bv.z; BsT[kq + 3][r] = bv.w;
        }
        __syncthreads();
        #pragma unroll
        for (int kk = 0; kk < 64; kk += 4) {
            float4 a0 = *(const float4*)&As[3 * ty + 0][kk];
            float4 a1 = *(const float4*)&As[3 * ty + 1][kk];
            float4 a2 = *(const float4*)&As[3 * ty + 2][kk];
            float4 b0v, b1v, b2v;
            b0v.x = BsT[kk + 0][3 * tx + 0]; b1v.x = BsT[kk + 0][3 * tx + 1]; b2v.x = BsT[kk + 0][3 * tx + 2];
            b0v.y = BsT[kk + 1][3 * tx + 0]; b1v.y = BsT[kk + 1][3 * tx + 1]; b2v.y = BsT[kk + 1][3 * tx + 2];
            b0v.z = BsT[kk + 2][3 * tx + 0]; b1v.z = BsT[kk + 2][3 * tx + 1]; b2v.z = BsT[kk + 2][3 * tx + 2];
            b0v.w = BsT[kk + 3][3 * tx + 0]; b1v.w = BsT[kk + 3][3 * tx + 1]; b2v.w = BsT[kk + 3][3 * tx + 2];
            FMAK(x) FMAK(y) FMAK(z) FMAK(w)
        }
        __syncthreads();
    }

    float accs[3][3] = {{acc00, acc01, acc02}, {acc10, acc11, acc12}, {acc20, acc21, acc22}};
    #pragma unroll
    for (int i2 = 0; i2 < 3; i2++) {
        #pragma unroll
        for (int j2 = 0; j2 < 3; j2++) {
            int r = r0 + 3 * ty + i2, c = c0 + 3 * tx + j2;
            float v = accs[i2][j2];
            g_d[kz][r * NROW + c] = v;
            g_d[kz][c * NROW + r] = v;
            if (r == c) g_sqp[kz * NROW + r] = v;
        }
    }
}

// ---------------------------------------------------------------------------
// block reduce float4 for 192 threads (6 warps)
// ---------------------------------------------------------------------------
__device__ __forceinline__ float4 bred4(float4 v, float4* buf, int tid) {
    int lane = tid & 31, wid = tid >> 5;
    #pragma unroll
    for (int o = 16; o > 0; o >>= 1) {
        v.x += __shfl_xor_sync(0xffffffffu, v.x, o);
        v.y += __shfl_xor_sync(0xffffffffu, v.y, o);
        v.z += __shfl_xor_sync(0xffffffffu, v.z, o);
        v.w += __shfl_xor_sync(0xffffffffu, v.w, o);
    }
    if (lane == 0) buf[wid] = v;
    __syncthreads();
    if (tid < 8) {
        float4 w = (tid < 6) ? buf[tid] : make_float4(0.f, 0.f, 0.f, 0.f);
        #pragma unroll
        for (int o = 4; o > 0; o >>= 1) {
            w.x += __shfl_xor_sync(0xffu, w.x, o);
            w.y += __shfl_xor_sync(0xffu, w.y, o);
            w.z += __shfl_xor_sync(0xffu, w.z, o);
            w.w += __shfl_xor_sync(0xffu, w.w, o);
        }
        if (tid == 0) buf[0] = w;
    }
    __syncthreads();
    float4 r = buf[0];
    __syncthreads();
    return r;
}

// ---------------------------------------------------------------------------
// Kernel 2: TWO blocks per row (grid 768, 192 threads). sb = half index.
// Both blocks run the full setup/sort (duplicated, overlapped); work split:
//   cross:    block sb owns j = sb*192 + tid (full window 191 via zbext)
//   pos/var:  block sb owns elements/positions [sb*192, ...)
// Cross term needs NO sort (any fixed order); zbext built in natural order
// right after ranks, so the sort scan hides behind the hot loop.
// partial = 2n*vsum_part - 4*C_part + P_part - Q_part; two partials sum to row.
// ---------------------------------------------------------------------------
__global__ __launch_bounds__(192) void row_kernel(const int* __restrict__ labels,
                                                  float* __restrict__ out) {
    __shared__ float2 zbext[NM1 + 191];         // natural order + wrap extension
    __shared__ float  zs[NM1], bs[NM1];         // sorted
    __shared__ short  gsA[NM1], geA[NM1];       // group bounds per sorted pos
    __shared__ int    cntw[12][52];             // 12 virtual warp slots
    __shared__ int    tot[52];
    __shared__ int    basev[52];
    __shared__ unsigned long long ymask;
    __shared__ float4 redbuf[6];
    __shared__ double dred[128];
    __shared__ int    isLast;

    int tid = threadIdx.x;
    int sb = blockIdx.x & 1;
    int i = blockIdx.x >> 1;
    int lane = tid & 31, wid = tid >> 5;
    bool v1 = tid < 191;                        // second element valid

    {
        int* cw = &cntw[0][0];
        for (int idx = tid; idx < 12 * 52; idx += 192) cw[idx] = 0;
        if (tid == 0) ymask = 0ull;
    }
    __syncthreads();

    int labi = labels[i >= BSZ ? i - BSZ : i];
    float sq_i = g_sqp[i] + g_sqp[NROW + i] + g_sqp[2 * NROW + i] + g_sqp[3 * NROW + i];

    // ---- element 0: p0 = tid ----
    float z0; int y0;
    {
        int jj = tid + (tid >= i);
        float dot = g_d[0][i * NROW + jj] + g_d[1][i * NROW + jj]
                  + g_d[2][i * NROW + jj] + g_d[3][i * NROW + jj];
        float sq_j = g_sqp[jj] + g_sqp[NROW + jj] + g_sqp[2 * NROW + jj] + g_sqp[3 * NROW + jj];
        z0 = sqrtf(fmaxf(sq_i + sq_j - 2.f * dot, 0.f));
        int labj = labels[jj >= BSZ ? jj - BSZ : jj];
        y0 = abs(labi - labj);
    }
    // ---- element 1: p1 = tid + 192 ----
    float z1 = 0.f; int y1 = 0;
    if (v1) {
        int p1 = tid + 192;
        int jj = p1 + (p1 >= i);
        float dot = g_d[0][i * NROW + jj] + g_d[1][i * NROW + jj]
                  + g_d[2][i * NROW + jj] + g_d[3][i * NROW + jj];
        float sq_j = g_sqp[jj] + g_sqp[NROW + jj] + g_sqp[2 * NROW + jj] + g_sqp[3 * NROW + jj];
        z1 = sqrtf(fmaxf(sq_i + sq_j - 2.f * dot, 0.f));
        int labj = labels[jj >= BSZ ? jj - BSZ : jj];
        y1 = abs(labi - labj);
    }

    atomicOr(&ymask, (1ull << y0) | (v1 ? (1ull << y1) : 0ull));

    unsigned mm0 = __match_any_sync(0xffffffffu, y0);
    if (lane == __ffs(mm0) - 1) atomicAdd(&cntw[wid][y0], __popc(mm0));
    unsigned mm1 = 0;
    if (v1) {
        mm1 = __match_any_sync(__activemask(), y1);
        if (lane == __ffs(mm1) - 1) atomicAdd(&cntw[6 + wid][y1], __popc(mm1));
    }
    __syncthreads();   // barrier A: counts + ymask complete

    float bp0 = 0.1f * (float)__popcll(ymask & ((1ull << y0) - 1ull));
    float bp1 = 0.1f * (float)__popcll(ymask & ((1ull << y1) - 1ull));

    // natural-order (z,b) + wrap extension  (cross term needs only this)
    zbext[tid] = make_float2(z0, bp0);
    if (v1) {
        zbext[tid + 192] = make_float2(z1, bp1);
        zbext[NM1 + tid] = make_float2(z0, bp0);   // elements 0..190 duplicated
    }
    if (tid < 52) {
        int s = 0;
        #pragma unroll
        for (int w2 = 0; w2 < 12; w2++) s += cntw[w2][tid];
        tot[tid] = s;
    }
    __syncthreads();   // barrier B: zbext + tot ready

    // tid0 runs the serial bin scan BEFORE its cross loop (hides behind others')
    if (tid == 0) {
        int run = 0;
        for (int v = 0; v < 52; v++) { basev[v] = run; run += tot[v]; }
    }

    // ---- cross term: j = sb*192 + tid, window k = j+1 .. j+191 ----
    float accC = 0.f;
    {
        int j = sb * 192 + tid;
        if (j < NM1) {
            float zj = sb ? z1 : z0;
            float bj = sb ? bp1 : bp0;
            unsigned long long nj = pk2(-zj, -bj);
            const unsigned long long* p = (const unsigned long long*)&zbext[j + 1];
            float ac0 = 0.f, ac1 = 0.f;
            #pragma unroll 2
            for (int q = 0; q < 190; q += 2) {
                unsigned long long va = p[q];
                unsigned long long vb = p[q + 1];
                ac0 += fabsf(mulhl(add2(va, nj)));
                ac1 += fabsf(mulhl(add2(vb, nj)));
            }
            ac0 += fabsf(mulhl(add2(p[190], nj)));
            accC = ac0 + ac1;
        }
    }
    __syncthreads();   // barrier C: basev ready (scan done before tid0's cross)

    // ---- counting-sort scatter (needed for pos term groups) ----
    {
        int before = 0;
        #pragma unroll
        for (int w2 = 0; w2 < 6; w2++)
            if (w2 < wid) before += cntw[w2][y0];
        int pos = basev[y0] + before + __popc(mm0 & ((1u << lane) - 1u));
        zs[pos] = z0; bs[pos] = bp0;
        gsA[pos] = (short)basev[y0];
        geA[pos] = (short)(basev[y0] + tot[y0]);
    }
    if (v1) {
        int before = 0;
        #pragma unroll
        for (int w2 = 0; w2 < 6; w2++) before += cntw[w2][y1];
        #pragma unroll
        for (int w2 = 6; w2 < 12; w2++)
            if (w2 < 6 + wid) before += cntw[w2][y1];
        int pos = basev[y1] + before + __popc(mm1 & ((1u << lane) - 1u));
        zs[pos] = z1; bs[pos] = bp1;
        gsA[pos] = (short)basev[y1];
        geA[pos] = (short)(basev[y1] + tot[y1]);
    }
    __syncthreads();   // barrier D: sorted arrays ready

    // ---- pos correction: this block owns sorted positions sb*192 + tid ----
    float accP = 0.f, accQ = 0.f;
    {
        int pp = sb * 192 + tid;
        if (pp < NM1) {
            float zj = zs[pp];
            int g0 = gsA[pp], g1 = geA[pp];
            for (int kk = g0; kk < g1; kk++) {
                float d = fabsf(zs[kk] - zj);
                accP += __fdividef(d, 1.0f + __expf(0.1f - d));
                accQ = fmaf(d, d, accQ);
            }
        }
    }

    // ---- means (identical in both blocks) + this block's variance part ----
    float4 s1 = bred4(make_float4(z0 + (v1 ? z1 : 0.f), bp0 + (v1 ? bp1 : 0.f), 0.f, 0.f),
                      redbuf, tid);
    float zm = s1.x * (1.0f / (float)NM1);
    float bm = s1.y * (1.0f / (float)NM1);
    float vsum = 0.f;
    if (sb == 0) {
        float dz0 = z0 - zm, db0 = bp0 - bm;
        vsum = dz0 * dz0 + db0 * db0;
    } else if (v1) {
        float dz1 = z1 - zm, db1 = bp1 - bm;
        vsum = dz1 * dz1 + db1 * db1;
    }

    float4 s2 = bred4(make_float4(vsum, accC, accP, accQ), redbuf, tid);

    if (tid == 0) {
        float part = (2.0f * (float)NM1) * s2.x - 4.0f * s2.y + s2.z - s2.w;
        g_row[blockIdx.x] = part;
    }

    // ---- fused final reduction: last of 768 blocks ----
    if (tid == 0) {
        __threadfence();
        int old = atomicAdd(&g_cnt, 1);
        isLast = (old == 2 * NROW - 1);
    }
    __syncthreads();
    if (isLast) {
        if (tid < 128) {
            double s = 0.0;
            #pragma unroll
            for (int q = 0; q < 6; q++) s += (double)g_row[tid + 128 * q];
            dred[tid] = s;
        }
        __syncthreads();
        #pragma unroll
        for (int st = 64; st > 0; st >>= 1) {
            if (tid < st) dred[tid] += dred[tid + st];
            __syncthreads();
        }
        if (tid == 0) {
            out[0] = (float)(dred[0] / MDEN);
            g_cnt = 0;                          // reset for graph replay
        }
    }
}

// ---------------------------------------------------------------------------
extern "C" void kernel_launch(void* const* d_in, const int* in_sizes, int n_in,
                              void* d_out, int out_size) {
    const float* features = (const float*)d_in[0];   // [192, 2, 1024] f32
    const int*   labels   = (const int*)d_in[1];     // [192, 1] i32
    (void)in_sizes; (void)n_in; (void)out_size;      // d_in[2] (ranks) unused

    gram_kernel<<<144, 256>>>(features);
    row_kernel<<<2 * NROW, 192>>>(labels, (float*)d_out);
}

// round 9
// speedup vs baseline: 1.0512x; 1.0512x over previous
#include <cuda_runtime.h>
#include <cuda_bf16.h>
#include <math.h>

// Problem constants
#define NROW 384          // N = 2*bs
#define BSZ  192
#define DIM  1024
#define NM1  383          // N-1
#define MDEN 56328576.0   // N*(N-1)^2
#define TK   48           // gram tile
#define NT   8            // tiles per side (384/48)

// Scratch (device globals; no allocation allowed)
__device__ float g_d[4][NROW * NROW];   // k-split partial dot products
__device__ float g_sqp[4 * NROW];       // k-split partial squared norms
__device__ float g_row[NROW];
__device__ int   g_cnt;                 // zero-init; last block resets -> replay-safe

__device__ __forceinline__ const float* frow(const float* f, int r) {
    return f + (r < BSZ ? r * (2 * DIM) : (r - BSZ) * (2 * DIM) + DIM);
}

// ---- packed f32x2 helpers ----
__device__ __forceinline__ unsigned long long pk2(float lo, float hi) {
    unsigned long long r;
    asm("mov.b64 %0, {%1, %2};" : "=l"(r) : "f"(lo), "f"(hi));
    return r;
}
__device__ __forceinline__ unsigned long long add2(unsigned long long a, unsigned long long b) {
    unsigned long long r;
    asm("add.rn.f32x2 %0, %1, %2;" : "=l"(r) : "l"(a), "l"(b));
    return r;
}
__device__ __forceinline__ unsigned long long fma2p(unsigned long long a, unsigned long long b,
                                                    unsigned long long c) {
    unsigned long long r;
    asm("fma.rn.f32x2 %0, %1, %2, %3;" : "=l"(r) : "l"(a), "l"(b), "l"(c));
    return r;
}
__device__ __forceinline__ unsigned long long abs2(unsigned long long a) {
    return a & 0x7FFFFFFF7FFFFFFFULL;
}
__device__ __forceinline__ float lanesum(unsigned long long a) {
    float lo, hi;
    asm("mov.b64 {%0, %1}, %2;" : "=f"(lo), "=f"(hi) : "l"(a));
    return lo + hi;
}

// ---------------------------------------------------------------------------
// Kernel 1: symmetric tiled Gram partials with k-split (unchanged).
// ---------------------------------------------------------------------------
#define FMAK(cmp) \
    acc00 = fmaf(a0.cmp, b0v.cmp, acc00); acc01 = fmaf(a0.cmp, b1v.cmp, acc01); acc02 = fmaf(a0.cmp, b2v.cmp, acc02); \
    acc10 = fmaf(a1.cmp, b0v.cmp, acc10); acc11 = fmaf(a1.cmp, b1v.cmp, acc11); acc12 = fmaf(a1.cmp, b2v.cmp, acc12); \
    acc20 = fmaf(a2.cmp, b0v.cmp, acc20); acc21 = fmaf(a2.cmp, b1v.cmp, acc21); acc22 = fmaf(a2.cmp, b2v.cmp, acc22);

__global__ __launch_bounds__(256) void gram_kernel(const float* __restrict__ feats) {
    __shared__ float As[TK][68];
    __shared__ float BsT[64][49];

    int bid = blockIdx.x;
    int p = bid >> 2, kz = bid & 3;
    int a = 0, rem = p;
    while (rem >= NT - a) { rem -= NT - a; a++; }
    int b = a + rem;

    int tid = threadIdx.x;
    int ty = tid >> 4, tx = tid & 15;
    int r0 = a * TK, c0 = b * TK;
    int kbase = kz * 256;

    float acc00 = 0.f, acc01 = 0.f, acc02 = 0.f;
    float acc10 = 0.f, acc11 = 0.f, acc12 = 0.f;
    float acc20 = 0.f, acc21 = 0.f, acc22 = 0.f;

    for (int ch = 0; ch < 4; ch++) {
        int kc = kbase + ch * 64;
        #pragma unroll
        for (int it = 0; it < 3; it++) {
            int q = tid + it * 256;
            int r = q >> 4, kq = (q & 15) << 2;
            float4 av = *(const float4*)(frow(feats, r0 + r) + kc + kq);
            float4 bv = *(const float4*)(frow(feats, c0 + r) + kc + kq);
            *(float4*)&As[r][kq] = av;
            BsT[kq + 0][r] = bv.x; BsT[kq + 1][r] = bv.y;
            BsT[kq + 2][r] = bv.z; BsT[kq + 3][r] = bv.w;
        }
        __syncthreads();
        #pragma unroll
        for (int kk = 0; kk < 64; kk += 4) {
            float4 a0 = *(const float4*)&As[3 * ty + 0][kk];
            float4 a1 = *(const float4*)&As[3 * ty + 1][kk];
            float4 a2 = *(const float4*)&As[3 * ty + 2][kk];
            float4 b0v, b1v, b2v;
            b0v.x = BsT[kk + 0][3 * tx + 0]; b1v.x = BsT[kk + 0][3 * tx + 1]; b2v.x = BsT[kk + 0][3 * tx + 2];
            b0v.y = BsT[kk + 1][3 * tx + 0]; b1v.y = BsT[kk + 1][3 * tx + 1]; b2v.y = BsT[kk + 1][3 * tx + 2];
            b0v.z = BsT[kk + 2][3 * tx + 0]; b1v.z = BsT[kk + 2][3 * tx + 1]; b2v.z = BsT[kk + 2][3 * tx + 2];
            b0v.w = BsT[kk + 3][3 * tx + 0]; b1v.w = BsT[kk + 3][3 * tx + 1]; b2v.w = BsT[kk + 3][3 * tx + 2];
            FMAK(x) FMAK(y) FMAK(z) FMAK(w)
        }
        __syncthreads();
    }

    float accs[3][3] = {{acc00, acc01, acc02}, {acc10, acc11, acc12}, {acc20, acc21, acc22}};
    #pragma unroll
    for (int i2 = 0; i2 < 3; i2++) {
        #pragma unroll
        for (int j2 = 0; j2 < 3; j2++) {
            int r = r0 + 3 * ty + i2, c = c0 + 3 * tx + j2;
            float v = accs[i2][j2];
            g_d[kz][r * NROW + c] = v;
            g_d[kz][c * NROW + r] = v;
            if (r == c) g_sqp[kz * NROW + r] = v;
        }
    }
}

// ---------------------------------------------------------------------------
// block reduce float4 for 384 threads (12 warps)
// ---------------------------------------------------------------------------
__device__ __forceinline__ float4 bred4(float4 v, float4* buf, int tid) {
    int lane = tid & 31, wid = tid >> 5;
    #pragma unroll
    for (int o = 16; o > 0; o >>= 1) {
        v.x += __shfl_xor_sync(0xffffffffu, v.x, o);
        v.y += __shfl_xor_sync(0xffffffffu, v.y, o);
        v.z += __shfl_xor_sync(0xffffffffu, v.z, o);
        v.w += __shfl_xor_sync(0xffffffffu, v.w, o);
    }
    if (lane == 0) buf[wid] = v;
    __syncthreads();
    if (tid < 16) {
        float4 w = (tid < 12) ? buf[tid] : make_float4(0.f, 0.f, 0.f, 0.f);
        #pragma unroll
        for (int o = 8; o > 0; o >>= 1) {
            w.x += __shfl_xor_sync(0xffffu, w.x, o);
            w.y += __shfl_xor_sync(0xffffu, w.y, o);
            w.z += __shfl_xor_sync(0xffffu, w.z, o);
            w.w += __shfl_xor_sync(0xffffu, w.w, o);
        }
        if (tid == 0) buf[0] = w;
    }
    __syncthreads();
    float4 r = buf[0];
    __syncthreads();
    return r;
}

// ---------------------------------------------------------------------------
// Kernel 2: one block per row, 384 threads (12 warps).
// Setup: one element per thread. Cross term over pair4[288] (natural order,
// each float4 = (z_a, z_{a+1}, b_a, b_{a+1}) for elements (2q, 2q+1) mod 383):
// thread (tp=tid>>1, half=tid&1) covers j-pair (2tp, 2tp+1), halves split the
// 95-read window -> 4 B of LDS per unordered pair, all 12 warps active.
// rowsum = 2n*(S2z+S2b) - 4*C_half + P - Q
// ---------------------------------------------------------------------------
__global__ __launch_bounds__(384) void row_kernel(const int* __restrict__ labels,
                                                  float* __restrict__ out) {
    __shared__ float4 pair4[288];               // natural-order element pairs (mod 383)
    __shared__ float  zs[NM1], bs[NM1];         // sorted (for pos term)
    __shared__ short  gsA[NM1], geA[NM1];       // group bounds per sorted pos
    __shared__ int    cntw[12][52];             // per-warp label-diff histogram
    __shared__ int    tot[52];
    __shared__ int    basev[52];
    __shared__ unsigned long long ymask;
    __shared__ float4 redbuf[12];
    __shared__ double dred[128];
    __shared__ int    isLast;

    int tid = threadIdx.x;
    int i = blockIdx.x;
    int lane = tid & 31, wid = tid >> 5;
    bool valid = tid < NM1;

    {
        int* cw = &cntw[0][0];
        for (int idx = tid; idx < 12 * 52; idx += 384) cw[idx] = 0;
        if (tid == 0) ymask = 0ull;
    }
    __syncthreads();

    int labi = labels[i >= BSZ ? i - BSZ : i];
    float sq_i = g_sqp[i] + g_sqp[NROW + i] + g_sqp[2 * NROW + i] + g_sqp[3 * NROW + i];

    // ---- element e = tid ----
    float z0 = 0.f; int y0 = 0;
    unsigned mm0 = 0;
    if (valid) {
        int jj = tid + (tid >= i);
        float dot = g_d[0][i * NROW + jj] + g_d[1][i * NROW + jj]
                  + g_d[2][i * NROW + jj] + g_d[3][i * NROW + jj];
        float sq_j = g_sqp[jj] + g_sqp[NROW + jj] + g_sqp[2 * NROW + jj] + g_sqp[3 * NROW + jj];
        z0 = sqrtf(fmaxf(sq_i + sq_j - 2.f * dot, 0.f));
        int labj = labels[jj >= BSZ ? jj - BSZ : jj];
        y0 = abs(labi - labj);
        atomicOr(&ymask, 1ull << y0);
        mm0 = __match_any_sync(__activemask(), y0);
        if (lane == __ffs(mm0) - 1) atomicAdd(&cntw[wid][y0], __popc(mm0));
    }
    __syncthreads();   // barrier A: counts + ymask complete

    float bp0 = 0.1f * (float)__popcll(ymask & ((1ull << y0) - 1ull));

    // ---- write pair4 (primary slot + wrap duplicate) ----
    if (valid) {
        int qp = tid >> 1;
        if (tid & 1) { pair4[qp].y = z0; pair4[qp].w = bp0; }
        else         { pair4[qp].x = z0; pair4[qp].z = bp0; }
        if (tid <= 192) {
            int qd = (tid + NM1) >> 1;         // 191..287
            if (tid & 1) { pair4[qd].x = z0; pair4[qd].z = bp0; }
            else         { pair4[qd].y = z0; pair4[qd].w = bp0; }
        }
    }
    if (tid < 52) {
        int s = 0;
        #pragma unroll
        for (int w2 = 0; w2 < 12; w2++) s += cntw[w2][tid];
        tot[tid] = s;
    }
    __syncthreads();   // barrier B: pair4 + tot ready

    // tid0's serial bin scan runs before its cross work (hidden under others')
    if (tid == 0) {
        int run = 0;
        for (int v = 0; v < 52; v++) { basev[v] = run; run += tot[v]; }
    }

    // ---- cross term ----
    float accC = 0.f;
    {
        int tp = tid >> 1, half = tid & 1;
        if (tp <= 190) {
            float4 jj4 = pair4[tp];            // (zj0, zj1, bj0, bj1)
            unsigned long long nz0 = pk2(-jj4.x, -jj4.x), nb0 = pk2(-jj4.z, -jj4.z);
            unsigned long long nz1 = pk2(-jj4.y, -jj4.y), nb1 = pk2(-jj4.w, -jj4.w);
            unsigned long long aA = 0ull, aB = 0ull;
            // window q in [tp+1, tp+95]; half0: first 47, half1: last 48
            int q0 = tp + 1 + 47 * half;
            unsigned int addr = (unsigned int)__cvta_generic_to_shared(&pair4[q0]);
            #pragma unroll 4
            for (int q = 0; q < 47; q++) {
                unsigned long long zk2, bk2;
                asm("ld.shared.v2.b64 {%0, %1}, [%2];" : "=l"(zk2), "=l"(bk2) : "r"(addr));
                addr += 16;
                aA = fma2p(abs2(add2(zk2, nz0)), abs2(add2(bk2, nb0)), aA);
                aB = fma2p(abs2(add2(zk2, nz1)), abs2(add2(bk2, nb1)), aB);
            }
            if (half) {
                // 48th window read (q = tp+95)
                unsigned long long zk2, bk2;
                asm("ld.shared.v2.b64 {%0, %1}, [%2];" : "=l"(zk2), "=l"(bk2) : "r"(addr));
                aA = fma2p(abs2(add2(zk2, nz0)), abs2(add2(bk2, nb0)), aA);
                aB = fma2p(abs2(add2(zk2, nz1)), abs2(add2(bk2, nb1)), aB);
                // trailing single for j1: element 2tp+192 mod 383
                float ze, be;
                if (tp <= 95) { float4 t = pair4[tp + 96]; ze = t.x; be = t.z; }
                else          { float4 t = pair4[tp - 96]; ze = t.y; be = t.w; }
                accC += fabsf((ze - jj4.y) * (be - jj4.w));
                // redistributed pair (382, tp)
                float4 t9 = pair4[191];        // (z382, z0, b382, b0)
                float4 tt = pair4[tp >> 1];
                float zt = (tp & 1) ? tt.y : tt.x;
                float bt = (tp & 1) ? tt.w : tt.z;
                accC += fabsf((t9.x - zt) * (t9.z - bt));
            } else {
                // edge pair (j0, j1)
                accC += fabsf((jj4.y - jj4.x) * (jj4.w - jj4.z));
            }
            accC += lanesum(aA) + lanesum(aB);
        }
    }
    __syncthreads();   // barrier C: basev ready

    // ---- counting-sort scatter (for pos term groups) ----
    if (valid) {
        int before = 0;
        #pragma unroll
        for (int w2 = 0; w2 < 12; w2++)
            if (w2 < wid) before += cntw[w2][y0];
        int pos = basev[y0] + before + __popc(mm0 & ((1u << lane) - 1u));
        zs[pos] = z0; bs[pos] = bp0;
        gsA[pos] = (short)basev[y0];
        geA[pos] = (short)(basev[y0] + tot[y0]);
    }
    __syncthreads();   // barrier D: sorted arrays ready

    // ---- pos correction: sorted position = tid ----
    float accP = 0.f, accQ = 0.f;
    if (valid) {
        float zj = zs[tid];
        int g0 = gsA[tid], g1 = geA[tid];
        for (int kk = g0; kk < g1; kk++) {
            float d = fabsf(zs[kk] - zj);
            accP += __fdividef(d, 1.0f + __expf(0.1f - d));
            accQ = fmaf(d, d, accQ);
        }
    }

    // ---- means + variance ----
    float4 s1 = bred4(make_float4(valid ? z0 : 0.f, valid ? bp0 : 0.f, 0.f, 0.f),
                      redbuf, tid);
    float zm = s1.x * (1.0f / (float)NM1);
    float bm = s1.y * (1.0f / (float)NM1);
    float vsum = 0.f;
    if (valid) {
        float dz = z0 - zm, db = bp0 - bm;
        vsum = dz * dz + db * db;
    }

    float4 s2 = bred4(make_float4(vsum, accC, accP, accQ), redbuf, tid);

    if (tid == 0) {
        float total = (2.0f * (float)NM1) * s2.x - 4.0f * s2.y + s2.z - s2.w;
        g_row[i] = total;
    }

    // ---- fused final reduction ----
    if (tid == 0) {
        __threadfence();
        int old = atomicAdd(&g_cnt, 1);
        isLast = (old == NROW - 1);
    }
    __syncthreads();
    if (isLast) {
        if (tid < 128) {
            dred[tid] = (double)g_row[tid] + (double)g_row[tid + 128]
                      + (double)g_row[tid + 256];
        }
        __syncthreads();
        #pragma unroll
        for (int st = 64; st > 0; st >>= 1) {
            if (tid < st) dred[tid] += dred[tid + st];
            __syncthreads();
        }
        if (tid == 0) {
            out[0] = (float)(dred[0] / MDEN);
            g_cnt = 0;                          // reset for graph replay
        }
    }
}

// ---------------------------------------------------------------------------
extern "C" void kernel_launch(void* const* d_in, const int* in_sizes, int n_in,
                              void* d_out, int out_size) {
    const float* features = (const float*)d_in[0];   // [192, 2, 1024] f32
    const int*   labels   = (const int*)d_in[1];     // [192, 1] i32
    (void)in_sizes; (void)n_in; (void)out_size;      // d_in[2] (ranks) unused

    gram_kernel<<<144, 256>>>(features);
    row_kernel<<<NROW, 384>>>(labels, (float*)d_out);
}

// round 10
// speedup vs baseline: 1.0719x; 1.0197x over previous
#include <cuda_runtime.h>
#include <cuda_bf16.h>
#include <math.h>

// Problem constants
#define NROW 384          // N = 2*bs
#define BSZ  192
#define DIM  1024
#define NM1  383          // N-1
#define MDEN 56328576.0   // N*(N-1)^2
#define TK   48           // gram tile
#define NT   8            // tiles per side (384/48)
#define SROW 70           // smem row stride (floats): conflict-free f32x2 reads

// Scratch (device globals; no allocation allowed)
__device__ float4 g_dv[NROW * NROW];    // packed kz-partial dot products
__device__ float4 g_sqv[NROW];          // packed kz-partial squared norms
__device__ float  g_row[NROW];
__device__ int    g_cnt;                // zero-init; last block resets -> replay-safe

__device__ __forceinline__ const float* frow(const float* f, int r) {
    return f + (r < BSZ ? r * (2 * DIM) : (r - BSZ) * (2 * DIM) + DIM);
}

// ---- packed f32x2 helpers ----
__device__ __forceinline__ unsigned long long pk2(float lo, float hi) {
    unsigned long long r;
    asm("mov.b64 %0, {%1, %2};" : "=l"(r) : "f"(lo), "f"(hi));
    return r;
}
__device__ __forceinline__ unsigned long long add2(unsigned long long a, unsigned long long b) {
    unsigned long long r;
    asm("add.rn.f32x2 %0, %1, %2;" : "=l"(r) : "l"(a), "l"(b));
    return r;
}
__device__ __forceinline__ unsigned long long fma2p(unsigned long long a, unsigned long long b,
                                                    unsigned long long c) {
    unsigned long long r;
    asm("fma.rn.f32x2 %0, %1, %2, %3;" : "=l"(r) : "l"(a), "l"(b), "l"(c));
    return r;
}
__device__ __forceinline__ unsigned long long abs2(unsigned long long a) {
    return a & 0x7FFFFFFF7FFFFFFFULL;
}
__device__ __forceinline__ float lanesum(unsigned long long a) {
    float lo, hi;
    asm("mov.b64 {%0, %1}, %2;" : "=f"(lo), "=f"(hi) : "l"(a));
    return lo + hi;
}

// ---------------------------------------------------------------------------
// Kernel 1: symmetric tiled Gram partials, packed-f32x2 inner loop.
// Grid = 36 tile-pairs * 4 k-slices = 144 blocks (one wave).
// As/Bs both row-major [48][70]; per 2-k step: 6 conflict-free LDS.64 +
// 9 FFMA2 (18 MACs). Epilogue writes kz component of float4 g_dv (+transpose)
// and the diagonal into g_sqv.
// ---------------------------------------------------------------------------
__global__ __launch_bounds__(256) void gram_kernel(const float* __restrict__ feats) {
    __shared__ float As[TK][SROW];
    __shared__ float Bs[TK][SROW];

    int bid = blockIdx.x;
    int p = bid >> 2, kz = bid & 3;
    int a = 0, rem = p;
    while (rem >= NT - a) { rem -= NT - a; a++; }
    int b = a + rem;

    int tid = threadIdx.x;
    int ty = tid >> 4, tx = tid & 15;
    int r0 = a * TK, c0 = b * TK;
    int kbase = kz * 256;

    unsigned long long acc[3][3] = {{0ull,0ull,0ull},{0ull,0ull,0ull},{0ull,0ull,0ull}};

    for (int ch = 0; ch < 4; ch++) {
        int kc = kbase + ch * 64;
        #pragma unroll
        for (int it = 0; it < 3; it++) {
            int q = tid + it * 256;
            int r = q >> 4, kq = (q & 15) << 2;
            float4 av = *(const float4*)(frow(feats, r0 + r) + kc + kq);
            float4 bv = *(const float4*)(frow(feats, c0 + r) + kc + kq);
            *(float2*)&As[r][kq]     = make_float2(av.x, av.y);
            *(float2*)&As[r][kq + 2] = make_float2(av.z, av.w);
            *(float2*)&Bs[r][kq]     = make_float2(bv.x, bv.y);
            *(float2*)&Bs[r][kq + 2] = make_float2(bv.z, bv.w);
        }
        __syncthreads();
        const unsigned long long* a0p = (const unsigned long long*)&As[3 * ty + 0][0];
        const unsigned long long* a1p = (const unsigned long long*)&As[3 * ty + 1][0];
        const unsigned long long* a2p = (const unsigned long long*)&As[3 * ty + 2][0];
        const unsigned long long* b0p = (const unsigned long long*)&Bs[3 * tx + 0][0];
        const unsigned long long* b1p = (const unsigned long long*)&Bs[3 * tx + 1][0];
        const unsigned long long* b2p = (const unsigned long long*)&Bs[3 * tx + 2][0];
        #pragma unroll
        for (int kk = 0; kk < 32; kk++) {
            unsigned long long a0 = a0p[kk], a1 = a1p[kk], a2 = a2p[kk];
            unsigned long long b0 = b0p[kk], b1 = b1p[kk], b2 = b2p[kk];
            acc[0][0] = fma2p(a0, b0, acc[0][0]);
            acc[0][1] = fma2p(a0, b1, acc[0][1]);
            acc[0][2] = fma2p(a0, b2, acc[0][2]);
            acc[1][0] = fma2p(a1, b0, acc[1][0]);
            acc[1][1] = fma2p(a1, b1, acc[1][1]);
            acc[1][2] = fma2p(a1, b2, acc[1][2]);
            acc[2][0] = fma2p(a2, b0, acc[2][0]);
            acc[2][1] = fma2p(a2, b1, acc[2][1]);
            acc[2][2] = fma2p(a2, b2, acc[2][2]);
        }
        __syncthreads();
    }

    #pragma unroll
    for (int i2 = 0; i2 < 3; i2++) {
        #pragma unroll
        for (int j2 = 0; j2 < 3; j2++) {
            int r = r0 + 3 * ty + i2, c = c0 + 3 * tx + j2;
            float v = lanesum(acc[i2][j2]);
            ((float*)&g_dv[r * NROW + c])[kz] = v;
            ((float*)&g_dv[c * NROW + r])[kz] = v;
            if (r == c) ((float*)&g_sqv[r])[kz] = v;
        }
    }
}

// ---------------------------------------------------------------------------
// block reduce float4 for 192 threads (6 warps)
// ---------------------------------------------------------------------------
__device__ __forceinline__ float4 bred4(float4 v, float4* buf, int tid) {
    int lane = tid & 31, wid = tid >> 5;
    #pragma unroll
    for (int o = 16; o > 0; o >>= 1) {
        v.x += __shfl_xor_sync(0xffffffffu, v.x, o);
        v.y += __shfl_xor_sync(0xffffffffu, v.y, o);
        v.z += __shfl_xor_sync(0xffffffffu, v.z, o);
        v.w += __shfl_xor_sync(0xffffffffu, v.w, o);
    }
    if (lane == 0) buf[wid] = v;
    __syncthreads();
    if (tid < 8) {
        float4 w = (tid < 6) ? buf[tid] : make_float4(0.f, 0.f, 0.f, 0.f);
        #pragma unroll
        for (int o = 4; o > 0; o >>= 1) {
            w.x += __shfl_xor_sync(0xffu, w.x, o);
            w.y += __shfl_xor_sync(0xffu, w.y, o);
            w.z += __shfl_xor_sync(0xffu, w.z, o);
            w.w += __shfl_xor_sync(0xffu, w.w, o);
        }
        if (tid == 0) buf[0] = w;
    }
    __syncthreads();
    float4 r = buf[0];
    __syncthreads();
    return r;
}

// ---------------------------------------------------------------------------
// Kernel 2 (R7 structure, best measured): 192 threads/block, one row/block.
// Each thread owns elements p0=tid, p1=tid+192 for setup, and the j-pair
// (2t, 2t+1) for the cross term over the extended pair array (no wrap).
// rowsum = 2n*(S2z+S2b) - 4*C_half + P - Q
// Only change vs R7: packed float4 gather from g_dv/g_sqv.
// ---------------------------------------------------------------------------
__global__ __launch_bounds__(192) void row_kernel(const int* __restrict__ labels,
                                                  float* __restrict__ out) {
    __shared__ float4 ext4[288];                // (z_a, z_{a+1}, b_a, b_{a+1})
    __shared__ float  zs[NM1], bs[NM1];         // sorted scalars
    __shared__ short  gsA[NM1], geA[NM1];       // group bounds per sorted pos
    __shared__ int    cntw[12][52];             // 12 virtual warp slots
    __shared__ int    tot[52];
    __shared__ int    basev[52];
    __shared__ unsigned long long ymask;
    __shared__ float4 redbuf[6];
    __shared__ double dred[128];
    __shared__ int    isLast;

    int tid = threadIdx.x;
    int i = blockIdx.x;
    int lane = tid & 31, wid = tid >> 5;
    bool v1 = tid < 191;                        // second element valid

    {
        int* cw = &cntw[0][0];
        for (int idx = tid; idx < 12 * 52; idx += 192) cw[idx] = 0;
        if (tid == 0) ymask = 0ull;
    }
    __syncthreads();

    int labi = labels[i >= BSZ ? i - BSZ : i];
    float4 svi = g_sqv[i];
    float sq_i = svi.x + svi.y + svi.z + svi.w;

    // ---- element 0: p0 = tid (always valid) ----
    float z0; int y0;
    {
        int jj = tid + (tid >= i);
        float4 dv = g_dv[i * NROW + jj];
        float4 sj = g_sqv[jj];
        float dot = dv.x + dv.y + dv.z + dv.w;
        float sq_j = sj.x + sj.y + sj.z + sj.w;
        z0 = sqrtf(fmaxf(sq_i + sq_j - 2.f * dot, 0.f));
        int labj = labels[jj >= BSZ ? jj - BSZ : jj];
        y0 = abs(labi - labj);
    }
    // ---- element 1: p1 = tid + 192 ----
    float z1 = 0.f; int y1 = 0;
    if (v1) {
        int p1 = tid + 192;
        int jj = p1 + (p1 >= i);
        float4 dv = g_dv[i * NROW + jj];
        float4 sj = g_sqv[jj];
        float dot = dv.x + dv.y + dv.z + dv.w;
        float sq_j = sj.x + sj.y + sj.z + sj.w;
        z1 = sqrtf(fmaxf(sq_i + sq_j - 2.f * dot, 0.f));
        int labj = labels[jj >= BSZ ? jj - BSZ : jj];
        y1 = abs(labi - labj);
    }

    atomicOr(&ymask, (1ull << y0) | (v1 ? (1ull << y1) : 0ull));

    unsigned mm0 = __match_any_sync(0xffffffffu, y0);
    if (lane == __ffs(mm0) - 1) atomicAdd(&cntw[wid][y0], __popc(mm0));
    unsigned mm1 = 0;
    if (v1) {
        mm1 = __match_any_sync(__activemask(), y1);
        if (lane == __ffs(mm1) - 1) atomicAdd(&cntw[6 + wid][y1], __popc(mm1));
    }
    __syncthreads();

    float bp0 = 0.1f * (float)__popcll(ymask & ((1ull << y0) - 1ull));
    float bp1 = 0.1f * (float)__popcll(ymask & ((1ull << y1) - 1ull));

    if (tid < 52) {
        int s = 0;
        #pragma unroll
        for (int w2 = 0; w2 < 12; w2++) s += cntw[w2][tid];
        tot[tid] = s;
    }
    __syncthreads();
    if (tid == 0) {
        int run = 0;
        for (int v = 0; v < 52; v++) { basev[v] = run; run += tot[v]; }
    }
    __syncthreads();

    // scatter element 0 (virtual warp = wid)
    {
        int before = 0;
        #pragma unroll
        for (int w2 = 0; w2 < 6; w2++)
            if (w2 < wid) before += cntw[w2][y0];
        int pos = basev[y0] + before + __popc(mm0 & ((1u << lane) - 1u));
        zs[pos] = z0; bs[pos] = bp0;
        gsA[pos] = (short)basev[y0];
        geA[pos] = (short)(basev[y0] + tot[y0]);
    }
    // scatter element 1 (virtual warp = 6 + wid)
    if (v1) {
        int before = 0;
        #pragma unroll
        for (int w2 = 0; w2 < 6; w2++) before += cntw[w2][y1];
        #pragma unroll
        for (int w2 = 6; w2 < 12; w2++)
            if (w2 < 6 + wid) before += cntw[w2][y1];
        int pos = basev[y1] + before + __popc(mm1 & ((1u << lane) - 1u));
        zs[pos] = z1; bs[pos] = bp1;
        gsA[pos] = (short)basev[y1];
        geA[pos] = (short)(basev[y1] + tot[y1]);
    }
    __syncthreads();

    // ---- build extended pair array: ext[q] covers elements (2q, 2q+1) mod 383
    {
        int a = 2 * tid; if (a >= NM1) a -= NM1;      // q = tid (a<=382)
        int b2 = a + 1;  if (b2 >= NM1) b2 -= NM1;
        ext4[tid] = make_float4(zs[a], zs[b2], bs[a], bs[b2]);
    }
    if (tid < 96) {
        int q = tid + 192;
        int a = 2 * q - NM1;                           // odd, 1..191
        ext4[q] = make_float4(zs[a], zs[a + 1], bs[a], bs[a + 1]);
    }
    __syncthreads();

    // ---- means + variance contributions ----
    float4 s1 = bred4(make_float4(z0 + (v1 ? z1 : 0.f), bp0 + (v1 ? bp1 : 0.f), 0.f, 0.f),
                      redbuf, tid);
    float zm = s1.x * (1.0f / (float)NM1);
    float bm = s1.y * (1.0f / (float)NM1);
    float dz0 = z0 - zm, db0 = bp0 - bm;
    float vsum = dz0 * dz0 + db0 * db0;
    if (v1) {
        float dz1 = z1 - zm, db1 = bp1 - bm;
        vsum += dz1 * dz1 + db1 * db1;
    }

    // ---- cross term: j0=2t, j1=2t+1 share 95 extended pairs [t+1 .. t+95] ----
    float accC = 0.f;
    if (tid <= 190) {
        int t = tid;
        float zj0 = zs[2 * t],     bj0 = bs[2 * t];
        float zj1 = zs[2 * t + 1], bj1 = bs[2 * t + 1];
        unsigned long long nz0 = pk2(-zj0, -zj0), nb0 = pk2(-bj0, -bj0);
        unsigned long long nz1 = pk2(-zj1, -zj1), nb1 = pk2(-bj1, -bj1);
        unsigned long long aA = 0ull, aB = 0ull;
        unsigned int addr = (unsigned int)__cvta_generic_to_shared(&ext4[t + 1]);
        #pragma unroll 5
        for (int q = 0; q < 95; q++) {
            unsigned long long zk2, bk2;
            asm("ld.shared.v2.b64 {%0, %1}, [%2];" : "=l"(zk2), "=l"(bk2) : "r"(addr));
            addr += 16;
            aA = fma2p(abs2(add2(zk2, nz0)), abs2(add2(bk2, nb0)), aA);
            aB = fma2p(abs2(add2(zk2, nz1)), abs2(add2(bk2, nb1)), aB);
        }
        accC = lanesum(aA) + lanesum(aB);
        // edge pair (j0, j1)
        accC += fabsf((zj1 - zj0) * (bj1 - bj0));
        // trailing single for j1: element 2t+192 (mod 383)
        {
            int ke = 2 * t + 192; if (ke >= NM1) ke -= NM1;
            accC += fabsf((zs[ke] - zj1) * (bs[ke] - bj1));
        }
        // redistributed pair (382, t)
        accC += fabsf((zs[382] - zs[t]) * (bs[382] - bs[t]));
    }

    // ---- pos correction: same-y groups of p0 and p1 ----
    float accP = 0.f, accQ = 0.f;
    {
        float zj = zs[tid];
        int g0 = gsA[tid], g1 = geA[tid];
        for (int kk = g0; kk < g1; kk++) {
            float d = fabsf(zs[kk] - zj);
            accP += __fdividef(d, 1.0f + __expf(0.1f - d));
            accQ = fmaf(d, d, accQ);
        }
    }
    if (v1) {
        int p1 = tid + 192;
        float zj = zs[p1];
        int g0 = gsA[p1], g1 = geA[p1];
        for (int kk = g0; kk < g1; kk++) {
            float d = fabsf(zs[kk] - zj);
            accP += __fdividef(d, 1.0f + __expf(0.1f - d));
            accQ = fmaf(d, d, accQ);
        }
    }

    float4 s2 = bred4(make_float4(vsum, accC, accP, accQ), redbuf, tid);

    if (tid == 0) {
        float total = (2.0f * (float)NM1) * s2.x - 4.0f * s2.y + s2.z - s2.w;
        g_row[i] = total;
    }

    // ---- fused final reduction ----
    if (tid == 0) {
        __threadfence();
        int old = atomicAdd(&g_cnt, 1);
        isLast = (old == NROW - 1);
    }
    __syncthreads();
    if (isLast) {
        if (tid < 128) {
            dred[tid] = (double)g_row[tid] + (double)g_row[tid + 128]
                      + (double)g_row[tid + 256];
        }
        __syncthreads();
        #pragma unroll
        for (int st = 64; st > 0; st >>= 1) {
            if (tid < st) dred[tid] += dred[tid + st];
            __syncthreads();
        }
        if (tid == 0) {
            out[0] = (float)(dred[0] / MDEN);
            g_cnt = 0;                          // reset for graph replay
        }
    }
}

// ---------------------------------------------------------------------------
extern "C" void kernel_launch(void* const* d_in, const int* in_sizes, int n_in,
                              void* d_out, int out_size) {
    const float* features = (const float*)d_in[0];   // [192, 2, 1024] f32
    const int*   labels   = (const int*)d_in[1];     // [192, 1] i32
    (void)in_sizes; (void)n_in; (void)out_size;      // d_in[2] (ranks) unused

    gram_kernel<<<144, 256>>>(features);
    row_kernel<<<NROW, 192>>>(labels, (float*)d_out);
}

// round 11
// speedup vs baseline: 1.1332x; 1.0572x over previous
#include <cuda_runtime.h>
#include <cuda_bf16.h>
#include <math.h>

// Problem constants
#define NROW 384          // N = 2*bs
#define BSZ  192
#define DIM  1024
#define NM1  383          // N-1
#define MDEN 56328576.0   // N*(N-1)^2
#define TK   48           // gram tile
#define NT   8            // tiles per side (384/48)
#define SROW 70           // smem row stride (floats): conflict-free f32x2 reads

// Scratch (device globals; no allocation allowed)
__device__ float g_d[4][NROW * NROW];   // per-kz partial dot planes (coalesced)
__device__ float g_sqp[4 * NROW];       // per-kz partial squared norms
__device__ float g_row[NROW];
__device__ int   g_cnt;                 // zero-init; last block resets -> replay-safe

__device__ __forceinline__ const float* frow(const float* f, int r) {
    return f + (r < BSZ ? r * (2 * DIM) : (r - BSZ) * (2 * DIM) + DIM);
}

// ---- packed f32x2 helpers ----
__device__ __forceinline__ unsigned long long pk2(float lo, float hi) {
    unsigned long long r;
    asm("mov.b64 %0, {%1, %2};" : "=l"(r) : "f"(lo), "f"(hi));
    return r;
}
__device__ __forceinline__ unsigned long long add2(unsigned long long a, unsigned long long b) {
    unsigned long long r;
    asm("add.rn.f32x2 %0, %1, %2;" : "=l"(r) : "l"(a), "l"(b));
    return r;
}
__device__ __forceinline__ unsigned long long fma2p(unsigned long long a, unsigned long long b,
                                                    unsigned long long c) {
    unsigned long long r;
    asm("fma.rn.f32x2 %0, %1, %2, %3;" : "=l"(r) : "l"(a), "l"(b), "l"(c));
    return r;
}
__device__ __forceinline__ unsigned long long abs2(unsigned long long a) {
    return a & 0x7FFFFFFF7FFFFFFFULL;
}
__device__ __forceinline__ float lanesum(unsigned long long a) {
    float lo, hi;
    asm("mov.b64 {%0, %1}, %2;" : "=f"(lo), "=f"(hi) : "l"(a));
    return lo + hi;
}

// ---------------------------------------------------------------------------
// Kernel 1: symmetric tiled Gram partials, packed-f32x2 inner loop,
// per-kz PLANE stores (coalesced-ish, no cross-block 16B interleave).
// Grid = 36 tile-pairs * 4 k-slices = 144 blocks (one wave).
// ---------------------------------------------------------------------------
__global__ __launch_bounds__(256) void gram_kernel(const float* __restrict__ feats) {
    __shared__ float As[TK][SROW];
    __shared__ float Bs[TK][SROW];

    int bid = blockIdx.x;
    int p = bid >> 2, kz = bid & 3;
    int a = 0, rem = p;
    while (rem >= NT - a) { rem -= NT - a; a++; }
    int b = a + rem;

    int tid = threadIdx.x;
    int ty = tid >> 4, tx = tid & 15;
    int r0 = a * TK, c0 = b * TK;
    int kbase = kz * 256;

    unsigned long long acc[3][3] = {{0ull,0ull,0ull},{0ull,0ull,0ull},{0ull,0ull,0ull}};

    for (int ch = 0; ch < 4; ch++) {
        int kc = kbase + ch * 64;
        #pragma unroll
        for (int it = 0; it < 3; it++) {
            int q = tid + it * 256;
            int r = q >> 4, kq = (q & 15) << 2;
            float4 av = *(const float4*)(frow(feats, r0 + r) + kc + kq);
            float4 bv = *(const float4*)(frow(feats, c0 + r) + kc + kq);
            *(float2*)&As[r][kq]     = make_float2(av.x, av.y);
            *(float2*)&As[r][kq + 2] = make_float2(av.z, av.w);
            *(float2*)&Bs[r][kq]     = make_float2(bv.x, bv.y);
            *(float2*)&Bs[r][kq + 2] = make_float2(bv.z, bv.w);
        }
        __syncthreads();
        const unsigned long long* a0p = (const unsigned long long*)&As[3 * ty + 0][0];
        const unsigned long long* a1p = (const unsigned long long*)&As[3 * ty + 1][0];
        const unsigned long long* a2p = (const unsigned long long*)&As[3 * ty + 2][0];
        const unsigned long long* b0p = (const unsigned long long*)&Bs[3 * tx + 0][0];
        const unsigned long long* b1p = (const unsigned long long*)&Bs[3 * tx + 1][0];
        const unsigned long long* b2p = (const unsigned long long*)&Bs[3 * tx + 2][0];
        #pragma unroll
        for (int kk = 0; kk < 32; kk++) {
            unsigned long long a0 = a0p[kk], a1 = a1p[kk], a2 = a2p[kk];
            unsigned long long b0 = b0p[kk], b1 = b1p[kk], b2 = b2p[kk];
            acc[0][0] = fma2p(a0, b0, acc[0][0]);
            acc[0][1] = fma2p(a0, b1, acc[0][1]);
            acc[0][2] = fma2p(a0, b2, acc[0][2]);
            acc[1][0] = fma2p(a1, b0, acc[1][0]);
            acc[1][1] = fma2p(a1, b1, acc[1][1]);
            acc[1][2] = fma2p(a1, b2, acc[1][2]);
            acc[2][0] = fma2p(a2, b0, acc[2][0]);
            acc[2][1] = fma2p(a2, b1, acc[2][1]);
            acc[2][2] = fma2p(a2, b2, acc[2][2]);
        }
        __syncthreads();
    }

    #pragma unroll
    for (int i2 = 0; i2 < 3; i2++) {
        #pragma unroll
        for (int j2 = 0; j2 < 3; j2++) {
            int r = r0 + 3 * ty + i2, c = c0 + 3 * tx + j2;
            float v = lanesum(acc[i2][j2]);
            g_d[kz][r * NROW + c] = v;
            g_d[kz][c * NROW + r] = v;
            if (r == c) g_sqp[kz * NROW + r] = v;
        }
    }
}

// ---------------------------------------------------------------------------
// block reduce float4 for 192 threads (6 warps)
// ---------------------------------------------------------------------------
__device__ __forceinline__ float4 bred4(float4 v, float4* buf, int tid) {
    int lane = tid & 31, wid = tid >> 5;
    #pragma unroll
    for (int o = 16; o > 0; o >>= 1) {
        v.x += __shfl_xor_sync(0xffffffffu, v.x, o);
        v.y += __shfl_xor_sync(0xffffffffu, v.y, o);
        v.z += __shfl_xor_sync(0xffffffffu, v.z, o);
        v.w += __shfl_xor_sync(0xffffffffu, v.w, o);
    }
    if (lane == 0) buf[wid] = v;
    __syncthreads();
    if (tid < 8) {
        float4 w = (tid < 6) ? buf[tid] : make_float4(0.f, 0.f, 0.f, 0.f);
        #pragma unroll
        for (int o = 4; o > 0; o >>= 1) {
            w.x += __shfl_xor_sync(0xffu, w.x, o);
            w.y += __shfl_xor_sync(0xffu, w.y, o);
            w.z += __shfl_xor_sync(0xffu, w.z, o);
            w.w += __shfl_xor_sync(0xffu, w.w, o);
        }
        if (tid == 0) buf[0] = w;
    }
    __syncthreads();
    float4 r = buf[0];
    __syncthreads();
    return r;
}

// ---------------------------------------------------------------------------
// Kernel 2 (R7 structure): 192 threads/block, one row/block.
// Changes vs R7: scatter writes ext4 directly (one less pass+barrier);
// warp-parallel 52-bin exclusive scan.
// rowsum = 2n*(S2z+S2b) - 4*C_half + P - Q
// ---------------------------------------------------------------------------
__global__ __launch_bounds__(192) void row_kernel(const int* __restrict__ labels,
                                                  float* __restrict__ out) {
    __shared__ float4 ext4[288];                // element pairs (2q, 2q+1 mod 383)
    __shared__ float  zs[NM1], bs[NM1];         // sorted scalars
    __shared__ short  gsA[NM1], geA[NM1];       // group bounds per sorted pos
    __shared__ int    cntw[12][52];             // 12 virtual warp slots
    __shared__ int    tot[52];
    __shared__ int    basev[52];
    __shared__ unsigned long long ymask;
    __shared__ float4 redbuf[6];
    __shared__ double dred[128];
    __shared__ int    isLast;

    int tid = threadIdx.x;
    int i = blockIdx.x;
    int lane = tid & 31, wid = tid >> 5;
    bool v1 = tid < 191;                        // second element valid

    {
        int* cw = &cntw[0][0];
        for (int idx = tid; idx < 12 * 52; idx += 192) cw[idx] = 0;
        if (tid == 0) ymask = 0ull;
    }
    __syncthreads();

    int labi = labels[i >= BSZ ? i - BSZ : i];
    float sq_i = g_sqp[i] + g_sqp[NROW + i] + g_sqp[2 * NROW + i] + g_sqp[3 * NROW + i];

    // ---- element 0: p0 = tid (always valid) ----
    float z0; int y0;
    {
        int jj = tid + (tid >= i);
        float dot = g_d[0][i * NROW + jj] + g_d[1][i * NROW + jj]
                  + g_d[2][i * NROW + jj] + g_d[3][i * NROW + jj];
        float sq_j = g_sqp[jj] + g_sqp[NROW + jj] + g_sqp[2 * NROW + jj] + g_sqp[3 * NROW + jj];
        z0 = sqrtf(fmaxf(sq_i + sq_j - 2.f * dot, 0.f));
        int labj = labels[jj >= BSZ ? jj - BSZ : jj];
        y0 = abs(labi - labj);
    }
    // ---- element 1: p1 = tid + 192 ----
    float z1 = 0.f; int y1 = 0;
    if (v1) {
        int p1 = tid + 192;
        int jj = p1 + (p1 >= i);
        float dot = g_d[0][i * NROW + jj] + g_d[1][i * NROW + jj]
                  + g_d[2][i * NROW + jj] + g_d[3][i * NROW + jj];
        float sq_j = g_sqp[jj] + g_sqp[NROW + jj] + g_sqp[2 * NROW + jj] + g_sqp[3 * NROW + jj];
        z1 = sqrtf(fmaxf(sq_i + sq_j - 2.f * dot, 0.f));
        int labj = labels[jj >= BSZ ? jj - BSZ : jj];
        y1 = abs(labi - labj);
    }

    atomicOr(&ymask, (1ull << y0) | (v1 ? (1ull << y1) : 0ull));

    unsigned mm0 = __match_any_sync(0xffffffffu, y0);
    if (lane == __ffs(mm0) - 1) atomicAdd(&cntw[wid][y0], __popc(mm0));
    unsigned mm1 = 0;
    if (v1) {
        mm1 = __match_any_sync(__activemask(), y1);
        if (lane == __ffs(mm1) - 1) atomicAdd(&cntw[6 + wid][y1], __popc(mm1));
    }
    __syncthreads();   // barrier A

    float bp0 = 0.1f * (float)__popcll(ymask & ((1ull << y0) - 1ull));
    float bp1 = 0.1f * (float)__popcll(ymask & ((1ull << y1) - 1ull));

    if (tid < 52) {
        int s = 0;
        #pragma unroll
        for (int w2 = 0; w2 < 12; w2++) s += cntw[w2][tid];
        tot[tid] = s;
    }
    __syncthreads();   // barrier B

    // warp-parallel exclusive scan of 52 bins (warp 0)
    if (tid < 32) {
        int a0 = tot[tid];
        int v = a0;
        #pragma unroll
        for (int o = 1; o < 32; o <<= 1) {
            int n = __shfl_up_sync(0xffffffffu, v, o);
            if (tid >= o) v += n;
        }
        basev[tid] = v - a0;
        int c32 = __shfl_sync(0xffffffffu, v, 31);
        int a1 = (tid < 20) ? tot[32 + tid] : 0;
        int w = a1;
        #pragma unroll
        for (int o = 1; o < 32; o <<= 1) {
            int n = __shfl_up_sync(0xffffffffu, w, o);
            if (tid >= o) w += n;
        }
        if (tid < 20) basev[32 + tid] = c32 + w - a1;
    }
    __syncthreads();   // barrier C

    // ---- scatter: sorted scalars + DIRECT ext4 component writes ----
    {
        int before = 0;
        #pragma unroll
        for (int w2 = 0; w2 < 6; w2++)
            if (w2 < wid) before += cntw[w2][y0];
        int pos = basev[y0] + before + __popc(mm0 & ((1u << lane) - 1u));
        zs[pos] = z0; bs[pos] = bp0;
        gsA[pos] = (short)basev[y0];
        geA[pos] = (short)(basev[y0] + tot[y0]);
        int qp = pos >> 1;
        if (pos & 1) { ext4[qp].y = z0; ext4[qp].w = bp0; }
        else         { ext4[qp].x = z0; ext4[qp].z = bp0; }
        if (pos <= 192) {
            int qd = (pos + NM1) >> 1;
            if (pos & 1) { ext4[qd].x = z0; ext4[qd].z = bp0; }
            else         { ext4[qd].y = z0; ext4[qd].w = bp0; }
        }
    }
    if (v1) {
        int before = 0;
        #pragma unroll
        for (int w2 = 0; w2 < 6; w2++) before += cntw[w2][y1];
        #pragma unroll
        for (int w2 = 6; w2 < 12; w2++)
            if (w2 < 6 + wid) before += cntw[w2][y1];
        int pos = basev[y1] + before + __popc(mm1 & ((1u << lane) - 1u));
        zs[pos] = z1; bs[pos] = bp1;
        gsA[pos] = (short)basev[y1];
        geA[pos] = (short)(basev[y1] + tot[y1]);
        int qp = pos >> 1;
        if (pos & 1) { ext4[qp].y = z1; ext4[qp].w = bp1; }
        else         { ext4[qp].x = z1; ext4[qp].z = bp1; }
        if (pos <= 192) {
            int qd = (pos + NM1) >> 1;
            if (pos & 1) { ext4[qd].x = z1; ext4[qd].z = bp1; }
            else         { ext4[qd].y = z1; ext4[qd].w = bp1; }
        }
    }
    __syncthreads();   // barrier D: sorted arrays + ext4 ready

    // ---- means + variance contributions ----
    float4 s1 = bred4(make_float4(z0 + (v1 ? z1 : 0.f), bp0 + (v1 ? bp1 : 0.f), 0.f, 0.f),
                      redbuf, tid);
    float zm = s1.x * (1.0f / (float)NM1);
    float bm = s1.y * (1.0f / (float)NM1);
    float dz0 = z0 - zm, db0 = bp0 - bm;
    float vsum = dz0 * dz0 + db0 * db0;
    if (v1) {
        float dz1 = z1 - zm, db1 = bp1 - bm;
        vsum += dz1 * dz1 + db1 * db1;
    }

    // ---- cross term: j0=2t, j1=2t+1 share 95 extended pairs [t+1 .. t+95] ----
    float accC = 0.f;
    if (tid <= 190) {
        int t = tid;
        float zj0 = zs[2 * t],     bj0 = bs[2 * t];
        float zj1 = zs[2 * t + 1], bj1 = bs[2 * t + 1];
        unsigned long long nz0 = pk2(-zj0, -zj0), nb0 = pk2(-bj0, -bj0);
        unsigned long long nz1 = pk2(-zj1, -zj1), nb1 = pk2(-bj1, -bj1);
        unsigned long long aA = 0ull, aB = 0ull;
        unsigned int addr = (unsigned int)__cvta_generic_to_shared(&ext4[t + 1]);
        #pragma unroll 5
        for (int q = 0; q < 95; q++) {
            unsigned long long zk2, bk2;
            asm("ld.shared.v2.b64 {%0, %1}, [%2];" : "=l"(zk2), "=l"(bk2) : "r"(addr));
            addr += 16;
            aA = fma2p(abs2(add2(zk2, nz0)), abs2(add2(bk2, nb0)), aA);
            aB = fma2p(abs2(add2(zk2, nz1)), abs2(add2(bk2, nb1)), aB);
        }
        accC = lanesum(aA) + lanesum(aB);
        // edge pair (j0, j1)
        accC += fabsf((zj1 - zj0) * (bj1 - bj0));
        // trailing single for j1: element 2t+192 (mod 383)
        {
            int ke = 2 * t + 192; if (ke >= NM1) ke -= NM1;
            accC += fabsf((zs[ke] - zj1) * (bs[ke] - bj1));
        }
        // redistributed pair (382, t)
        accC += fabsf((zs[382] - zs[t]) * (bs[382] - bs[t]));
    }

    // ---- pos correction: same-y groups of p0 and p1 ----
    float accP = 0.f, accQ = 0.f;
    {
        float zj = zs[tid];
        int g0 = gsA[tid], g1 = geA[tid];
        for (int kk = g0; kk < g1; kk++) {
            float d = fabsf(zs[kk] - zj);
            accP += __fdividef(d, 1.0f + __expf(0.1f - d));
            accQ = fmaf(d, d, accQ);
        }
    }
    if (v1) {
        int p1 = tid + 192;
        float zj = zs[p1];
        int g0 = gsA[p1], g1 = geA[p1];
        for (int kk = g0; kk < g1; kk++) {
            float d = fabsf(zs[kk] - zj);
            accP += __fdividef(d, 1.0f + __expf(0.1f - d));
            accQ = fmaf(d, d, accQ);
        }
    }

    float4 s2 = bred4(make_float4(vsum, accC, accP, accQ), redbuf, tid);

    if (tid == 0) {
        float total = (2.0f * (float)NM1) * s2.x - 4.0f * s2.y + s2.z - s2.w;
        g_row[i] = total;
    }

    // ---- fused final reduction ----
    if (tid == 0) {
        __threadfence();
        int old = atomicAdd(&g_cnt, 1);
        isLast = (old == NROW - 1);
    }
    __syncthreads();
    if (isLast) {
        if (tid < 128) {
            dred[tid] = (double)g_row[tid] + (double)g_row[tid + 128]
                      + (double)g_row[tid + 256];
        }
        __syncthreads();
        #pragma unroll
        for (int st = 64; st > 0; st >>= 1) {
            if (tid < st) dred[tid] += dred[tid + st];
            __syncthreads();
        }
        if (tid == 0) {
            out[0] = (float)(dred[0] / MDEN);
            g_cnt = 0;                          // reset for graph replay
        }
    }
}

// ---------------------------------------------------------------------------
extern "C" void kernel_launch(void* const* d_in, const int* in_sizes, int n_in,
                              void* d_out, int out_size) {
    const float* features = (const float*)d_in[0];   // [192, 2, 1024] f32
    const int*   labels   = (const int*)d_in[1];     // [192, 1] i32
    (void)in_sizes; (void)n_in; (void)out_size;      // d_in[2] (ranks) unused

    gram_kernel<<<144, 256>>>(features);
    row_kernel<<<NROW, 192>>>(labels, (float*)d_out);
}